// round 2
// baseline (speedup 1.0000x reference)
#include <cuda_runtime.h>
#include <cstdint>

// ----------------------------------------------------------------------------
// BasePatchOrthogonalMix: y = fold( unfold(x) @ W^T )
// Pure GEMM: out[m, e] = sum_d patch[m, d] * W[e, d]
//   m = (b, hp, wp)   : 16 * 64 * 64 = 65536
//   d/e = (c, ph, pw) : 64 * 4 * 4   = 1024
// x[b,c,h,w] row-major; patch element (m, d) = x[b, c, hp*4+ph, wp*4+pw]
// -> per (m, c, ph): 4 contiguous floats (pw) => float4 gather/scatter.
//
// Strategy (R1): warp-mma m16n8k8 tf32, CTA tile 128x128x32, 8 warps (2x4),
// warp tile 64x32. LDG -> cvt.rna.tf32 -> STS staging (register double
// buffer). cvt.rna is REQUIRED: tf32 truncation has a -2^-10 systematic bias
// that alone blows the 1e-3 rel-err budget.
// ----------------------------------------------------------------------------

#define THREADS 256
#define PADK    36            // 32 + 4: (m*36 + k) % 32 = (4m + k) % 32 -> conflict-free frags
#define ABUF    (128 * PADK)  // floats per buffer per matrix
#define SMEM_BYTES (4 * ABUF * 4)   // 2 matrices x 2 buffers = 73728 B

__device__ __forceinline__ uint32_t f2tf32(float f) {
    uint32_t u;
    asm("cvt.rna.tf32.f32 %0, %1;" : "=r"(u) : "f"(f));
    return u;
}

__device__ __forceinline__ float4 cvt4(float4 v) {
    float4 t;
    t.x = __uint_as_float(f2tf32(v.x));
    t.y = __uint_as_float(f2tf32(v.y));
    t.z = __uint_as_float(f2tf32(v.z));
    t.w = __uint_as_float(f2tf32(v.w));
    return t;
}

__device__ __forceinline__ void mma_tf32(float d[4], const uint32_t a[4], const uint32_t b[2]) {
    asm volatile(
        "mma.sync.aligned.m16n8k8.row.col.f32.tf32.tf32.f32 "
        "{%0,%1,%2,%3}, {%4,%5,%6,%7}, {%8,%9}, {%0,%1,%2,%3};\n"
        : "+f"(d[0]), "+f"(d[1]), "+f"(d[2]), "+f"(d[3])
        : "r"(a[0]), "r"(a[1]), "r"(a[2]), "r"(a[3]),
          "r"(b[0]), "r"(b[1]));
}

__global__ void __launch_bounds__(THREADS)
patch_mix_kernel(const float* __restrict__ x,
                 const float* __restrict__ Wm,
                 float*       __restrict__ y)
{
    extern __shared__ float smem[];
    float* As = smem;              // [2][128][PADK]
    float* Bs = smem + 2 * ABUF;   // [2][128][PADK]

    const int tid  = threadIdx.x;
    const int bN   = blockIdx.x;   // 0..7   (N tiles; inner -> W stays in L2)
    const int bM   = blockIdx.y;   // 0..511 (M tiles)

    const int lane = tid & 31;
    const int warp = tid >> 5;
    const int gid  = lane >> 2;    // groupID (0..7)
    const int tig  = lane & 3;     // thread-in-group
    const int wMo  = (warp >> 2) * 64;  // warp m offset (0 / 64)
    const int wNo  = (warp & 3) * 32;   // warp n offset (0/32/64/96)

    // ---- staging mapping: thread handles row mA, 4 float4 chunks k4 = 2l + hsel
    const int mA   = tid & 127;
    const int hsel = tid >> 7;

    const int m_g = bM * 128 + mA;
    const int bb  = m_g >> 12;        // batch
    const int hp  = (m_g >> 6) & 63;  // patch row
    const int wp  = m_g & 63;         // patch col

    const float* pA[4];
    const float* pB[4];
    int sAB[4];
#pragma unroll
    for (int l = 0; l < 4; ++l) {
        int k4   = 2 * l + hsel;      // float4 index within 32-wide K tile
        int coff = k4 >> 2;           // channel offset within K tile (0/1)
        int ph   = k4 & 3;            // patch-row within patch
        // x + (bb*64 + c)*65536 + (hp*4+ph)*256 + wp*4 ; c = kt*2 + coff
        pA[l] = x + (((size_t)(bb * 64 + coff)) << 16) + ((hp * 4 + ph) << 8) + wp * 4;
        pB[l] = Wm + (size_t)(bN * 128 + mA) * 1024 + k4 * 4;
        sAB[l] = mA * PADK + k4 * 4;
    }

    float4 av[4], bv[4];
    float acc[4][4][4];
#pragma unroll
    for (int i = 0; i < 4; ++i)
#pragma unroll
        for (int j = 0; j < 4; ++j)
#pragma unroll
            for (int r = 0; r < 4; ++r) acc[i][j][r] = 0.0f;

    // ---- prologue: stage kt = 0 into buffer 0
#pragma unroll
    for (int l = 0; l < 4; ++l) {
        av[l] = *(const float4*)(pA[l]);
        bv[l] = *(const float4*)(pB[l]);
    }
#pragma unroll
    for (int l = 0; l < 4; ++l) {
        *(float4*)(As + sAB[l]) = cvt4(av[l]);
        *(float4*)(Bs + sAB[l]) = cvt4(bv[l]);
    }
    __syncthreads();

    // ---- mainloop over K tiles
    for (int kt = 0; kt < 32; ++kt) {
        const int cur = kt & 1;

        if (kt < 31) {
            // A advances 2 channels per K tile: 2*65536 floats
#pragma unroll
            for (int l = 0; l < 4; ++l) {
                av[l] = *(const float4*)(pA[l] + (size_t)(kt + 1) * 131072);
                bv[l] = *(const float4*)(pB[l] + (kt + 1) * 32);
            }
        }

        const float* Ab = As + cur * ABUF;
        const float* Bb = Bs + cur * ABUF;
#pragma unroll
        for (int ks = 0; ks < 4; ++ks) {
            uint32_t af[4][4], bf[4][2];
            const int kc = ks * 8 + tig;
#pragma unroll
            for (int mt = 0; mt < 4; ++mt) {
                int r = wMo + mt * 16 + gid;
                af[mt][0] = __float_as_uint(Ab[r * PADK + kc]);
                af[mt][1] = __float_as_uint(Ab[(r + 8) * PADK + kc]);
                af[mt][2] = __float_as_uint(Ab[r * PADK + kc + 4]);
                af[mt][3] = __float_as_uint(Ab[(r + 8) * PADK + kc + 4]);
            }
#pragma unroll
            for (int nt = 0; nt < 4; ++nt) {
                int rn = wNo + nt * 8 + gid;
                bf[nt][0] = __float_as_uint(Bb[rn * PADK + kc]);
                bf[nt][1] = __float_as_uint(Bb[rn * PADK + kc + 4]);
            }
#pragma unroll
            for (int mt = 0; mt < 4; ++mt)
#pragma unroll
                for (int nt = 0; nt < 4; ++nt)
                    mma_tf32(acc[mt][nt], af[mt], bf[nt]);
        }

        if (kt < 31) {
            const int nxt = cur ^ 1;
#pragma unroll
            for (int l = 0; l < 4; ++l) {
                *(float4*)(As + nxt * ABUF + sAB[l]) = cvt4(av[l]);
                *(float4*)(Bs + nxt * ABUF + sAB[l]) = cvt4(bv[l]);
            }
            __syncthreads();
        }
    }

    // ---- epilogue: scatter accumulators to y[b, c, h, w]
    // C frag: c0/c1 at (row=gid, col=2*tig, 2*tig+1); c2/c3 at row=gid+8.
    // e = c*16 + ph*4 + pw ; col pair -> pw, pw+1 contiguous => float2 store.
#pragma unroll
    for (int mt = 0; mt < 4; ++mt) {
#pragma unroll
        for (int h = 0; h < 2; ++h) {
            int m_out = bM * 128 + wMo + mt * 16 + gid + h * 8;
            int ob  = m_out >> 12;
            int ohp = (m_out >> 6) & 63;
            int owp = m_out & 63;
            float* ybase = y + (((size_t)ob) << 22) + (ohp << 10) + owp * 4;
#pragma unroll
            for (int nt = 0; nt < 4; ++nt) {
                int e   = bN * 128 + wNo + nt * 8 + 2 * tig;
                int ce  = e >> 4;
                int oph = (e >> 2) & 3;
                int opw = e & 3;          // 0 or 2 -> float2 aligned
                float2 v;
                v.x = acc[mt][nt][h * 2];
                v.y = acc[mt][nt][h * 2 + 1];
                *(float2*)(ybase + (ce << 16) + (oph << 8) + opw) = v;
            }
        }
    }
}

extern "C" void kernel_launch(void* const* d_in, const int* in_sizes, int n_in,
                              void* d_out, int out_size)
{
    const float* x  = (const float*)d_in[0];
    const float* Wm = (const float*)d_in[1];
    float*       y  = (float*)d_out;

    // 72 KB dynamic smem > 48 KB default; attribute call is idempotent,
    // not a stream op, and allocation-free -> graph-capture safe.
    cudaFuncSetAttribute(patch_mix_kernel,
                         cudaFuncAttributeMaxDynamicSharedMemorySize, SMEM_BYTES);

    dim3 grid(8, 512);   // N tiles inner -> all 8 CTAs of a row share the A tile in L2
    patch_mix_kernel<<<grid, THREADS, SMEM_BYTES>>>(x, Wm, y);
}

// round 4
// speedup vs baseline: 2.2829x; 2.2829x over previous
#include <cuda_runtime.h>
#include <cstdint>

// ----------------------------------------------------------------------------
// BasePatchOrthogonalMix as one GEMM: out[m,e] = sum_d patch[m,d] * W[e,d]
//   m = (b,hp,wp) = 65536,  d/e = (c,ph,pw) = 1024
//
// R3: two kernels in one binary.
//  * patch_mix_tc  — tcgen05 (kind::tf32) SS GEMM, CTA tile 256x256xK32, TMEM
//    accumulators (512 cols). Compiled ONLY under arch-specific (sm_103a)
//    feature passes; other passes get a stub (ptxas-clean everywhere).
//  * patch_mix_fb  — proven R1 warp-mma m16n8k8 fallback (1274 us).
//  kernel_launch dispatches via cudaFuncGetAttributes(numRegs) on patch_mix_tc:
//  the runtime reports the binary chosen for THIS device, so stub => fallback.
//
// cvt.rna.tf32 staging is REQUIRED in both paths: tf32 truncation carries a
// ~2^-10 systematic bias that alone blows the 1e-3 rel-err budget.
// ----------------------------------------------------------------------------

#if defined(__CUDA_ARCH__) && (defined(__CUDA_ARCH_FEAT_SM103_ALL) || defined(__CUDA_ARCH_FEAT_SM100_ALL))
#define TCGEN05_OK 1
#else
#define TCGEN05_OK 0
#endif

// ======================== common helpers ====================================

__device__ __forceinline__ uint32_t f2tf32(float f) {
    uint32_t u;
    asm("cvt.rna.tf32.f32 %0, %1;" : "=r"(u) : "f"(f));
    return u;
}

__device__ __forceinline__ float4 cvt4(float4 v) {
    float4 t;
    t.x = __uint_as_float(f2tf32(v.x));
    t.y = __uint_as_float(f2tf32(v.y));
    t.z = __uint_as_float(f2tf32(v.z));
    t.w = __uint_as_float(f2tf32(v.w));
    return t;
}

__device__ __forceinline__ uint32_t smem_u32(const void* p) {
    uint32_t a;
    asm("{ .reg .u64 t; cvta.to.shared.u64 t, %1; cvt.u32.u64 %0, t; }" : "=r"(a) : "l"(p));
    return a;
}

// ======================== tcgen05 path ======================================

#define TC_THREADS     256
#define TC_TILE_M      256
#define TC_TILE_N      256
#define TC_KTILE       32
#define TC_NKT         32
#define TC_STAGES      3
#define TC_A_BYTES     (TC_TILE_M * 128)
#define TC_B_BYTES     (TC_TILE_N * 128)
#define TC_STAGE_BYTES (TC_A_BYTES + TC_B_BYTES)          // 65536
#define TC_SMEM_CTRL   1024
#define TC_SMEM_BYTES  (TC_SMEM_CTRL + TC_STAGES * TC_STAGE_BYTES)   // 197632

// idesc kind::tf32: dtype=F32(1)<<4, atype=TF32(2)<<7, btype=TF32(2)<<10,
// n_dim=N>>3 at [17:23) (6 bits, 256->32 fits), m_dim=M>>4 at [24:29) (M=128)
#define TC_IDESC  ((1u << 4) | (2u << 7) | (2u << 10) | ((TC_TILE_N / 8) << 17) | ((128 / 16) << 24))

// K-major SW128 smem desc base: layout=2<<61, version=1<<46, SBO=64<<32, LBO=1<<16
#define TC_DESC_BASE ((2ull << 61) | (1ull << 46) | (64ull << 32) | (1ull << 16))

#if TCGEN05_OK
__device__ __forceinline__ uint32_t elect_one() {
    uint32_t p;
    asm volatile("{ .reg .pred p; elect.sync _|p, 0xFFFFFFFF; selp.b32 %0, 1, 0, p; }" : "=r"(p));
    return p;
}

__device__ __forceinline__ uint64_t make_desc(uint32_t addr) {
    return TC_DESC_BASE | ((uint64_t)(addr >> 4) & 0x3FFF);
}

__device__ __forceinline__ void mma_tf32_ss(uint32_t d_tmem, uint64_t ad, uint64_t bd,
                                            uint32_t en) {
    asm volatile(
        "{\n\t.reg .pred p;\n\tsetp.ne.u32 p, %4, 0;\n\t"
        "tcgen05.mma.cta_group::1.kind::tf32 [%0], %1, %2, %3, p;\n\t}"
        :: "r"(d_tmem), "l"(ad), "l"(bd), "r"(TC_IDESC), "r"(en) : "memory");
}

__device__ __forceinline__ void mbar_init(uint32_t a, uint32_t cnt) {
    asm volatile("mbarrier.init.shared.b64 [%0], %1;" :: "r"(a), "r"(cnt) : "memory");
}

__device__ __forceinline__ void mbar_wait(uint32_t a, uint32_t parity) {
    uint32_t done;
    asm volatile(
        "{\n\t.reg .pred p;\n\t"
        "mbarrier.try_wait.parity.acquire.cta.shared::cta.b64 p, [%1], %2;\n\t"
        "selp.b32 %0, 1, 0, p;\n\t}"
        : "=r"(done) : "r"(a), "r"(parity) : "memory");
    if (!done) {
        asm volatile(
            "{\n\t.reg .pred P1;\n\t"
            "WL_%=:\n\t"
            "mbarrier.try_wait.parity.acquire.cta.shared::cta.b64 P1, [%0], %1, 0x989680;\n\t"
            "@P1 bra.uni WD_%=;\n\t"
            "bra.uni WL_%=;\n\t"
            "WD_%=:\n\t}"
            :: "r"(a), "r"(parity) : "memory");
    }
}

__device__ __forceinline__ void tc_stage(const float* __restrict__ pA,
                                         const float* __restrict__ pB,
                                         int kt, char* As, char* Bs,
                                         const uint32_t* s8) {
    float4 a[8], b[8];
#pragma unroll
    for (int k4 = 0; k4 < 8; ++k4) {
        // A (m, k): k = kt*32 + k4*4 + i  ->  channel kt*2+(k4>>2), ph=k4&3, pw=i
        a[k4] = *(const float4*)(pA + (((size_t)(kt * 2 + (k4 >> 2))) << 16) + ((k4 & 3) << 8));
        b[k4] = *(const float4*)(pB + kt * TC_KTILE + k4 * 4);
    }
#pragma unroll
    for (int k4 = 0; k4 < 8; ++k4) {
        *(float4*)(As + s8[k4]) = cvt4(a[k4]);
        *(float4*)(Bs + s8[k4]) = cvt4(b[k4]);
    }
}
#endif  // TCGEN05_OK

__global__ void __launch_bounds__(TC_THREADS, 1)
patch_mix_tc(const float* __restrict__ x,
             const float* __restrict__ Wm,
             float*       __restrict__ y)
{
#if TCGEN05_OK
    extern __shared__ char smem[];
    const uint32_t smem_base = smem_u32(smem);
    const int tid  = threadIdx.x;
    const int warp = tid >> 5;
    const int lane = tid & 31;
    const int bN   = blockIdx.x;   // 0..3  (inner -> A tile L2 reuse)
    const int bM   = blockIdx.y;   // 0..255

    // ---- TMEM alloc (512 cols: D0 = cols 0..255 (M rows 0..127), D1 = 256..511)
    if (warp == 0) {
        asm volatile("tcgen05.alloc.cta_group::1.sync.aligned.shared::cta.b32 [%0], %1;"
                     :: "r"(smem_base), "r"(512u) : "memory");
    }
    if (tid == 0) {
        mbar_init(smem_base + 16, 1);
        mbar_init(smem_base + 24, 1);
        mbar_init(smem_base + 32, 1);
    }
    __syncthreads();
    uint32_t tmem;
    asm volatile("ld.shared.b32 %0, [%1];" : "=r"(tmem) : "r"(smem_base));

    // ---- staging: thread t stages A row t and B row t (8 x float4 each)
    const int m_g = bM * TC_TILE_M + tid;
    const int bb  = m_g >> 12;
    const int hp  = (m_g >> 6) & 63;
    const int wp  = m_g & 63;
    const float* pA = x + (((size_t)bb) << 22) + (hp << 10) + wp * 4;
    const float* pB = Wm + (size_t)(bN * TC_TILE_N + tid) * 1024;

    uint32_t s8[8];
#pragma unroll
    for (int k4 = 0; k4 < 8; ++k4) {
        uint32_t bo = (uint32_t)tid * 128 + k4 * 16;
        s8[k4] = bo ^ ((bo >> 3) & 0x70);   // SW128 swizzle, 16B granules
    }

    char* Abuf[TC_STAGES];
    char* Bbuf[TC_STAGES];
    uint32_t Aaddr[TC_STAGES], Baddr[TC_STAGES];
#pragma unroll
    for (int s = 0; s < TC_STAGES; ++s) {
        Abuf[s] = smem + TC_SMEM_CTRL + s * TC_STAGE_BYTES;
        Bbuf[s] = Abuf[s] + TC_A_BYTES;
        Aaddr[s] = smem_base + TC_SMEM_CTRL + s * TC_STAGE_BYTES;
        Baddr[s] = Aaddr[s] + TC_A_BYTES;
    }

    // ---- prologue: stage kt = 0, 1
    tc_stage(pA, pB, 0, Abuf[0], Bbuf[0], s8);
    tc_stage(pA, pB, 1, Abuf[1], Bbuf[1], s8);
    asm volatile("fence.proxy.async.shared::cta;" ::: "memory");
    __syncthreads();

    int wcnt0 = 0, wcnt1 = 0, wcnt2 = 0;

    for (int kt = 0; kt < TC_NKT; ++kt) {
        const int s = kt % TC_STAGES;

        if (warp == 0) {
            asm volatile("tcgen05.fence::after_thread_sync;" ::: "memory");
            if (elect_one()) {
                uint64_t aD = make_desc(Aaddr[s]);
                uint64_t bD = make_desc(Baddr[s]);
#pragma unroll
                for (int h = 0; h < 2; ++h) {
#pragma unroll
                    for (int ks = 0; ks < 4; ++ks) {
                        // M-half h: +128 rows * 128B = +1024 desc units (16B)
                        mma_tf32_ss(tmem + h * 256,
                                    aD + h * 1024 + ks * 2,
                                    bD + ks * 2,
                                    (kt > 0 || ks > 0) ? 1u : 0u);
                    }
                }
                asm volatile(
                    "tcgen05.commit.cta_group::1.mbarrier::arrive::one.shared::cluster.b64 [%0];"
                    :: "r"(smem_base + 16 + 8 * (uint32_t)s) : "memory");
            }
        }

        const int kn = kt + 2;
        if (kn < TC_NKT) {
            const int sn = kn % TC_STAGES;
            if (kt >= 1) {   // buffer sn was consumed by MMAs committed at kt-1
                if (sn == 0)      { mbar_wait(smem_base + 16, wcnt0 & 1); wcnt0++; }
                else if (sn == 1) { mbar_wait(smem_base + 24, wcnt1 & 1); wcnt1++; }
                else              { mbar_wait(smem_base + 32, wcnt2 & 1); wcnt2++; }
            }
            tc_stage(pA, pB, kn, Abuf[sn], Bbuf[sn], s8);
            asm volatile("fence.proxy.async.shared::cta;" ::: "memory");
            __syncthreads();
        }
    }

    // last commit is kt=31 -> mbar[31%3=1]; completion is in-order.
    mbar_wait(smem_base + 24, wcnt1 & 1);
    asm volatile("tcgen05.fence::after_thread_sync;" ::: "memory");

    // ---- epilogue: TMEM -> y. warps 0..3: M rows 0..127 (D0); 4..7: 128..255 (D1)
    {
        const int h = warp >> 2;
        const uint32_t tm = tmem + h * 256;
        const int mo = bM * TC_TILE_M + h * 128 + (warp & 3) * 32 + lane;
        const int ob  = mo >> 12;
        const int ohp = (mo >> 6) & 63;
        const int owp = mo & 63;
        float* yb = y + (((size_t)ob) << 22) + (ohp << 10) + owp * 4;

#pragma unroll
        for (int q = 0; q < 4; ++q) {
            uint32_t d[64];
            asm volatile(
                "tcgen05.ld.sync.aligned.32x32b.x32.b32 "
                "{%0,%1,%2,%3,%4,%5,%6,%7,%8,%9,%10,%11,%12,%13,%14,%15,"
                "%16,%17,%18,%19,%20,%21,%22,%23,%24,%25,%26,%27,%28,%29,%30,%31}, [%32];"
                : "=r"(d[0]), "=r"(d[1]), "=r"(d[2]), "=r"(d[3]), "=r"(d[4]), "=r"(d[5]),
                  "=r"(d[6]), "=r"(d[7]), "=r"(d[8]), "=r"(d[9]), "=r"(d[10]), "=r"(d[11]),
                  "=r"(d[12]), "=r"(d[13]), "=r"(d[14]), "=r"(d[15]), "=r"(d[16]), "=r"(d[17]),
                  "=r"(d[18]), "=r"(d[19]), "=r"(d[20]), "=r"(d[21]), "=r"(d[22]), "=r"(d[23]),
                  "=r"(d[24]), "=r"(d[25]), "=r"(d[26]), "=r"(d[27]), "=r"(d[28]), "=r"(d[29]),
                  "=r"(d[30]), "=r"(d[31])
                : "r"(tm + q * 64));
            asm volatile(
                "tcgen05.ld.sync.aligned.32x32b.x32.b32 "
                "{%0,%1,%2,%3,%4,%5,%6,%7,%8,%9,%10,%11,%12,%13,%14,%15,"
                "%16,%17,%18,%19,%20,%21,%22,%23,%24,%25,%26,%27,%28,%29,%30,%31}, [%32];"
                : "=r"(d[32]), "=r"(d[33]), "=r"(d[34]), "=r"(d[35]), "=r"(d[36]), "=r"(d[37]),
                  "=r"(d[38]), "=r"(d[39]), "=r"(d[40]), "=r"(d[41]), "=r"(d[42]), "=r"(d[43]),
                  "=r"(d[44]), "=r"(d[45]), "=r"(d[46]), "=r"(d[47]), "=r"(d[48]), "=r"(d[49]),
                  "=r"(d[50]), "=r"(d[51]), "=r"(d[52]), "=r"(d[53]), "=r"(d[54]), "=r"(d[55]),
                  "=r"(d[56]), "=r"(d[57]), "=r"(d[58]), "=r"(d[59]), "=r"(d[60]), "=r"(d[61]),
                  "=r"(d[62]), "=r"(d[63])
                : "r"(tm + q * 64 + 32));
            asm volatile("tcgen05.wait::ld.sync.aligned;" ::: "memory");

            const int ebase = bN * TC_TILE_N + q * 64;   // multiple of 64
#pragma unroll
            for (int c4 = 0; c4 < 4; ++c4) {
                const int ce = (ebase >> 4) + c4;
#pragma unroll
                for (int ph = 0; ph < 4; ++ph) {
                    float4 v;
                    v.x = __uint_as_float(d[c4 * 16 + ph * 4 + 0]);
                    v.y = __uint_as_float(d[c4 * 16 + ph * 4 + 1]);
                    v.z = __uint_as_float(d[c4 * 16 + ph * 4 + 2]);
                    v.w = __uint_as_float(d[c4 * 16 + ph * 4 + 3]);
                    *(float4*)(yb + (((size_t)ce) << 16) + (ph << 8)) = v;
                }
            }
        }
    }

    asm volatile("tcgen05.fence::before_thread_sync;" ::: "memory");
    __syncthreads();
    if (warp == 0) {
        asm volatile("tcgen05.relinquish_alloc_permit.cta_group::1.sync.aligned;");
        asm volatile("tcgen05.dealloc.cta_group::1.sync.aligned.b32 %0, %1;"
                     :: "r"(tmem), "r"(512u));
    }
#else
    // Stub for non-arch-specific passes (never launched on those binaries).
    (void)x; (void)Wm; (void)y;
#endif
}

// ======================== fallback: proven R1 warp-mma ======================

#define FB_THREADS 256
#define FB_PADK    36
#define FB_ABUF    (128 * FB_PADK)
#define FB_SMEM_BYTES (4 * FB_ABUF * 4)   // 73728

__device__ __forceinline__ void fb_mma(float d[4], const uint32_t a[4], const uint32_t b[2]) {
    asm volatile(
        "mma.sync.aligned.m16n8k8.row.col.f32.tf32.tf32.f32 "
        "{%0,%1,%2,%3}, {%4,%5,%6,%7}, {%8,%9}, {%0,%1,%2,%3};\n"
        : "+f"(d[0]), "+f"(d[1]), "+f"(d[2]), "+f"(d[3])
        : "r"(a[0]), "r"(a[1]), "r"(a[2]), "r"(a[3]),
          "r"(b[0]), "r"(b[1]));
}

__global__ void __launch_bounds__(FB_THREADS)
patch_mix_fb(const float* __restrict__ x,
             const float* __restrict__ Wm,
             float*       __restrict__ y)
{
    extern __shared__ float smemf[];
    float* As = smemf;
    float* Bs = smemf + 2 * FB_ABUF;

    const int tid  = threadIdx.x;
    const int bN   = blockIdx.x;
    const int bM   = blockIdx.y;

    const int lane = tid & 31;
    const int warp = tid >> 5;
    const int gid  = lane >> 2;
    const int tig  = lane & 3;
    const int wMo  = (warp >> 2) * 64;
    const int wNo  = (warp & 3) * 32;

    const int mA   = tid & 127;
    const int hsel = tid >> 7;

    const int m_g = bM * 128 + mA;
    const int bb  = m_g >> 12;
    const int hp  = (m_g >> 6) & 63;
    const int wp  = m_g & 63;

    const float* pA[4];
    const float* pB[4];
    int sAB[4];
#pragma unroll
    for (int l = 0; l < 4; ++l) {
        int k4   = 2 * l + hsel;
        int coff = k4 >> 2;
        int ph   = k4 & 3;
        pA[l] = x + (((size_t)(bb * 64 + coff)) << 16) + ((hp * 4 + ph) << 8) + wp * 4;
        pB[l] = Wm + (size_t)(bN * 128 + mA) * 1024 + k4 * 4;
        sAB[l] = mA * FB_PADK + k4 * 4;
    }

    float4 av[4], bv[4];
    float acc[4][4][4];
#pragma unroll
    for (int i = 0; i < 4; ++i)
#pragma unroll
        for (int j = 0; j < 4; ++j)
#pragma unroll
            for (int r = 0; r < 4; ++r) acc[i][j][r] = 0.0f;

#pragma unroll
    for (int l = 0; l < 4; ++l) {
        av[l] = *(const float4*)(pA[l]);
        bv[l] = *(const float4*)(pB[l]);
    }
#pragma unroll
    for (int l = 0; l < 4; ++l) {
        *(float4*)(As + sAB[l]) = cvt4(av[l]);
        *(float4*)(Bs + sAB[l]) = cvt4(bv[l]);
    }
    __syncthreads();

    for (int kt = 0; kt < 32; ++kt) {
        const int cur = kt & 1;

        if (kt < 31) {
#pragma unroll
            for (int l = 0; l < 4; ++l) {
                av[l] = *(const float4*)(pA[l] + (size_t)(kt + 1) * 131072);
                bv[l] = *(const float4*)(pB[l] + (kt + 1) * 32);
            }
        }

        const float* Ab = As + cur * FB_ABUF;
        const float* Bb = Bs + cur * FB_ABUF;
#pragma unroll
        for (int ks = 0; ks < 4; ++ks) {
            uint32_t af[4][4], bf[4][2];
            const int kc = ks * 8 + tig;
#pragma unroll
            for (int mt = 0; mt < 4; ++mt) {
                int r = wMo + mt * 16 + gid;
                af[mt][0] = __float_as_uint(Ab[r * FB_PADK + kc]);
                af[mt][1] = __float_as_uint(Ab[(r + 8) * FB_PADK + kc]);
                af[mt][2] = __float_as_uint(Ab[r * FB_PADK + kc + 4]);
                af[mt][3] = __float_as_uint(Ab[(r + 8) * FB_PADK + kc + 4]);
            }
#pragma unroll
            for (int nt = 0; nt < 4; ++nt) {
                int rn = wNo + nt * 8 + gid;
                bf[nt][0] = __float_as_uint(Bb[rn * FB_PADK + kc]);
                bf[nt][1] = __float_as_uint(Bb[rn * FB_PADK + kc + 4]);
            }
#pragma unroll
            for (int mt = 0; mt < 4; ++mt)
#pragma unroll
                for (int nt = 0; nt < 4; ++nt)
                    fb_mma(acc[mt][nt], af[mt], bf[nt]);
        }

        if (kt < 31) {
            const int nxt = cur ^ 1;
#pragma unroll
            for (int l = 0; l < 4; ++l) {
                *(float4*)(As + nxt * FB_ABUF + sAB[l]) = cvt4(av[l]);
                *(float4*)(Bs + nxt * FB_ABUF + sAB[l]) = cvt4(bv[l]);
            }
            __syncthreads();
        }
    }

#pragma unroll
    for (int mt = 0; mt < 4; ++mt) {
#pragma unroll
        for (int h = 0; h < 2; ++h) {
            int m_out = bM * 128 + wMo + mt * 16 + gid + h * 8;
            int ob  = m_out >> 12;
            int ohp = (m_out >> 6) & 63;
            int owp = m_out & 63;
            float* ybase = y + (((size_t)ob) << 22) + (ohp << 10) + owp * 4;
#pragma unroll
            for (int nt = 0; nt < 4; ++nt) {
                int e   = bN * 128 + wNo + nt * 8 + 2 * tig;
                int ce  = e >> 4;
                int oph = (e >> 2) & 3;
                int opw = e & 3;
                float2 v;
                v.x = acc[mt][nt][h * 2];
                v.y = acc[mt][nt][h * 2 + 1];
                *(float2*)(ybase + (ce << 16) + (oph << 8) + opw) = v;
            }
        }
    }
}

// ======================== dispatch ==========================================

extern "C" void kernel_launch(void* const* d_in, const int* in_sizes, int n_in,
                              void* d_out, int out_size)
{
    const float* x  = (const float*)d_in[0];
    const float* Wm = (const float*)d_in[1];
    float*       y  = (float*)d_out;

    // Runtime probe: attributes reflect the binary selected for THIS device.
    // Real tcgen05 body => ~100+ regs; compute_103 stub => a handful.
    cudaFuncAttributes attr{};
    bool use_tc = false;
    if (cudaFuncGetAttributes(&attr, (const void*)patch_mix_tc) == cudaSuccess)
        use_tc = (attr.numRegs >= 40);

    if (use_tc) {
        cudaFuncSetAttribute(patch_mix_tc,
                             cudaFuncAttributeMaxDynamicSharedMemorySize, TC_SMEM_BYTES);
        dim3 grid(4, 256);   // N inner: 4 CTAs per bM row share the A tile in L2
        patch_mix_tc<<<grid, TC_THREADS, TC_SMEM_BYTES>>>(x, Wm, y);
    } else {
        cudaFuncSetAttribute(patch_mix_fb,
                             cudaFuncAttributeMaxDynamicSharedMemorySize, FB_SMEM_BYTES);
        dim3 grid(8, 512);
        patch_mix_fb<<<grid, FB_THREADS, FB_SMEM_BYTES>>>(x, Wm, y);
    }
}